// round 7
// baseline (speedup 1.0000x reference)
#include <cuda_runtime.h>
#include <math.h>

#define NV 2
#define NB 16384
#define NC 100
#define ND 512
#define ROWS_PER_WARP 4
#define ROWS_PER_BLOCK 32                        // 8 warps * 4 rows
#define BLOCKS_PER_V (NB / ROWS_PER_BLOCK)       // 512
#define MAIN_BLOCKS (NV * BLOCKS_PER_V)          // 1024
#define MARGIN_F 10.0f

// Scratch (no dynamic allocation allowed)
__device__ float g_partials[MAIN_BLOCKS];        // per-block diff^2 partial sums
__device__ float g_inter[NV];                    // per-v inter_loss

__global__ void __launch_bounds__(256) anchor_loss_main(
    const float* __restrict__ feat,
    const int* __restrict__ label,               // int32 (JAX x64 disabled)
    const float* __restrict__ anchor,
    float* __restrict__ out)                     // out[0]=loss, out[1..]=sims
{
    if (blockIdx.x < MAIN_BLOCKS) {
        // ---- main pass: 4 rows per warp (independent chains for MLP) ----
        const int warp = threadIdx.x >> 5;
        const int lane = threadIdx.x & 31;
        const int base = blockIdx.x * ROWS_PER_BLOCK + warp * ROWS_PER_WARP;
        const int v    = base >> 14;

        const float4* f4[ROWS_PER_WARP];
        const float4* c4[ROWS_PER_WARP];
        #pragma unroll
        for (int j = 0; j < ROWS_PER_WARP; j++) {
            int r = base + j;
            int b = r & (NB - 1);
            int l = min(max(label[b], 0), NC - 1);
            f4[j] = reinterpret_cast<const float4*>(feat) + (size_t)r * (ND / 4);
            c4[j] = reinterpret_cast<const float4*>(anchor)
                    + ((size_t)v * NC + l) * (ND / 4);
        }

        float dt[ROWS_PER_WARP], fn[ROWS_PER_WARP], cn[ROWS_PER_WARP];
        #pragma unroll
        for (int j = 0; j < ROWS_PER_WARP; j++) { dt[j] = 0.f; fn[j] = 0.f; cn[j] = 0.f; }

        #pragma unroll
        for (int k = 0; k < 4; k++) {
            #pragma unroll
            for (int j = 0; j < ROWS_PER_WARP; j++) {
                float4 f = f4[j][lane + 32 * k];
                float4 c = c4[j][lane + 32 * k];
                dt[j] = fmaf(f.x, c.x, fmaf(f.y, c.y, fmaf(f.z, c.z, fmaf(f.w, c.w, dt[j]))));
                fn[j] = fmaf(f.x, f.x, fmaf(f.y, f.y, fmaf(f.z, f.z, fmaf(f.w, f.w, fn[j]))));
                cn[j] = fmaf(c.x, c.x, fmaf(c.y, c.y, fmaf(c.z, c.z, fmaf(c.w, c.w, cn[j]))));
            }
        }
        #pragma unroll
        for (int off = 16; off > 0; off >>= 1) {
            #pragma unroll
            for (int j = 0; j < ROWS_PER_WARP; j++) {
                dt[j] += __shfl_xor_sync(0xffffffffu, dt[j], off);
                fn[j] += __shfl_xor_sync(0xffffffffu, fn[j], off);
                cn[j] += __shfl_xor_sync(0xffffffffu, cn[j], off);
            }
        }

        __shared__ float sh[8];
        if (lane == 0) {
            float dsum = 0.f;
            #pragma unroll
            for (int j = 0; j < ROWS_PER_WARP; j++) {
                float den = fmaxf(sqrtf(fn[j]), 1e-8f) * fmaxf(sqrtf(cn[j]), 1e-8f);
                out[1 + base + j] = dt[j] / den;
                dsum += fn[j] - 2.f * dt[j] + cn[j];   // ||f-c||^2
            }
            sh[warp] = dsum;
        }
        __syncthreads();
        if (threadIdx.x == 0) {
            float t = 0.f;
            #pragma unroll
            for (int w = 0; w < 8; w++) t += sh[w];
            g_partials[blockIdx.x] = t;
        }
    } else {
        // ---- anchor stats: one block per v ----
        // pair_sum = C * sum_c ||a_c||^2 - ||sum_c a_c||^2 (pd diagonal is 0)
        const int v = blockIdx.x - MAIN_BLOCKS;
        const int t = threadIdx.x;          // 0..255, covers d and d+256
        const float* a = anchor + (size_t)v * NC * ND;

        float m0 = 0.f, m1 = 0.f, s = 0.f;
        #pragma unroll 4
        for (int c = 0; c < NC; c++) {
            float x0 = a[(size_t)c * ND + t];
            float x1 = a[(size_t)c * ND + t + 256];
            m0 += x0; m1 += x1;
            s = fmaf(x0, x0, fmaf(x1, x1, s));
        }
        float q = fmaf(m0, m0, m1 * m1);

        __shared__ float shs[256], shq[256];
        shs[t] = s; shq[t] = q;
        __syncthreads();
        #pragma unroll
        for (int off = 128; off > 0; off >>= 1) {
            if (t < off) { shs[t] += shs[t + off]; shq[t] += shq[t + off]; }
            __syncthreads();
        }
        if (t == 0) {
            float S = shs[0];          // sum_c ||a_c||^2
            float M2 = shq[0];         // ||sum_c a_c||^2
            float inter = (NC * S - M2) / (float)(NC * (NC - 1));
            g_inter[v] = fmaxf(MARGIN_F - inter, 0.0f);
        }
    }
}

__global__ void __launch_bounds__(256) anchor_loss_finalize(float* __restrict__ out)
{
    // PDL: launch overlaps with primary; block here until primary completes.
    cudaGridDependencySynchronize();

    const int t = threadIdx.x;  // 256 threads; 512 partials per v
    float t0 = 0.f, t1 = 0.f;
    #pragma unroll
    for (int k = 0; k < 2; k++) {
        t0 += g_partials[t + 256 * k];                        // v = 0
        t1 += g_partials[BLOCKS_PER_V + t + 256 * k];         // v = 1
    }
    __shared__ float s0[256], s1[256];
    s0[t] = t0; s1[t] = t1;
    __syncthreads();
    #pragma unroll
    for (int off = 128; off > 0; off >>= 1) {
        if (t < off) { s0[t] += s0[t + off]; s1[t] += s1[t + off]; }
        __syncthreads();
    }
    if (t == 0) {
        float center_mean = (s0[0] + s1[0]) / (2.0f * (float)NV * (float)NB);
        float inter_mean  = (g_inter[0] + g_inter[1]) / (float)NV;
        out[0] = center_mean + inter_mean;
    }
}

extern "C" void kernel_launch(void* const* d_in, const int* in_sizes, int n_in,
                              void* d_out, int out_size)
{
    const float* feat   = (const float*)d_in[0];
    const int*   label  = (const int*)d_in[1];
    const float* anchor = (const float*)d_in[2];
    float* out = (float*)d_out;

    anchor_loss_main<<<MAIN_BLOCKS + NV, 256>>>(feat, label, anchor, out);

    // Finalize with Programmatic Dependent Launch: its launch setup overlaps
    // with the primary kernel; the dependency wait happens on-device.
    cudaLaunchConfig_t cfg = {};
    cfg.gridDim  = dim3(1, 1, 1);
    cfg.blockDim = dim3(256, 1, 1);
    cfg.dynamicSmemBytes = 0;
    cfg.stream = 0;
    cudaLaunchAttribute attrs[1];
    attrs[0].id = cudaLaunchAttributeProgrammaticStreamSerialization;
    attrs[0].val.programmaticStreamSerializationAllowed = 1;
    cfg.attrs = attrs;
    cfg.numAttrs = 1;
    cudaLaunchKernelEx(&cfg, anchor_loss_finalize, out);
}

// round 8
// speedup vs baseline: 1.0118x; 1.0118x over previous
#include <cuda_runtime.h>
#include <math.h>

#define NV 2
#define NB 16384
#define NC 100
#define ND 512
#define ROWS_PER_WARP 2
#define ROWS_PER_BLOCK 16                        // 8 warps * 2 rows
#define BLOCKS_PER_V (NB / ROWS_PER_BLOCK)       // 1024
#define MAIN_BLOCKS (NV * BLOCKS_PER_V)          // 2048
#define MARGIN_F 10.0f

// Scratch (no dynamic allocation allowed)
__device__ float g_partials[MAIN_BLOCKS];        // per-block diff^2 partial sums
__device__ float g_inter[NV];                    // per-v inter_loss

__global__ void __launch_bounds__(256) anchor_loss_main(
    const float* __restrict__ feat,
    const int* __restrict__ label,               // int32 (JAX x64 disabled)
    const float* __restrict__ anchor,
    float* __restrict__ out)                     // out[0]=loss, out[1..]=sims
{
    if (blockIdx.x < MAIN_BLOCKS) {
        // ---- main pass: 2 rows per warp (independent chains for MLP) ----
        const int warp = threadIdx.x >> 5;
        const int lane = threadIdx.x & 31;
        const int r0   = blockIdx.x * ROWS_PER_BLOCK + warp * ROWS_PER_WARP;
        const int r1   = r0 + 1;
        const int v    = r0 >> 14;
        const int b0   = r0 & (NB - 1);
        const int b1   = r1 & (NB - 1);

        const float4* f4a = reinterpret_cast<const float4*>(feat) + (size_t)r0 * (ND / 4);
        const float4* f4b = reinterpret_cast<const float4*>(feat) + (size_t)r1 * (ND / 4);
        int l0 = min(max(__ldg(&label[b0]), 0), NC - 1);
        int l1 = min(max(__ldg(&label[b1]), 0), NC - 1);
        const float4* c4a = reinterpret_cast<const float4*>(anchor)
                            + ((size_t)v * NC + l0) * (ND / 4);
        const float4* c4b = reinterpret_cast<const float4*>(anchor)
                            + ((size_t)v * NC + l1) * (ND / 4);

        float dt0 = 0.f, fn0 = 0.f, cn0 = 0.f;
        float dt1 = 0.f, fn1 = 0.f, cn1 = 0.f;
        #pragma unroll
        for (int k = 0; k < 4; k++) {
            float4 f0 = f4a[lane + 32 * k];
            float4 f1 = f4b[lane + 32 * k];
            float4 c0 = c4a[lane + 32 * k];
            float4 c1 = c4b[lane + 32 * k];
            dt0 = fmaf(f0.x, c0.x, fmaf(f0.y, c0.y, fmaf(f0.z, c0.z, fmaf(f0.w, c0.w, dt0))));
            fn0 = fmaf(f0.x, f0.x, fmaf(f0.y, f0.y, fmaf(f0.z, f0.z, fmaf(f0.w, f0.w, fn0))));
            cn0 = fmaf(c0.x, c0.x, fmaf(c0.y, c0.y, fmaf(c0.z, c0.z, fmaf(c0.w, c0.w, cn0))));
            dt1 = fmaf(f1.x, c1.x, fmaf(f1.y, c1.y, fmaf(f1.z, c1.z, fmaf(f1.w, c1.w, dt1))));
            fn1 = fmaf(f1.x, f1.x, fmaf(f1.y, f1.y, fmaf(f1.z, f1.z, fmaf(f1.w, f1.w, fn1))));
            cn1 = fmaf(c1.x, c1.x, fmaf(c1.y, c1.y, fmaf(c1.z, c1.z, fmaf(c1.w, c1.w, cn1))));
        }
        #pragma unroll
        for (int off = 16; off > 0; off >>= 1) {
            dt0 += __shfl_xor_sync(0xffffffffu, dt0, off);
            fn0 += __shfl_xor_sync(0xffffffffu, fn0, off);
            cn0 += __shfl_xor_sync(0xffffffffu, cn0, off);
            dt1 += __shfl_xor_sync(0xffffffffu, dt1, off);
            fn1 += __shfl_xor_sync(0xffffffffu, fn1, off);
            cn1 += __shfl_xor_sync(0xffffffffu, cn1, off);
        }

        __shared__ float sh[8];
        if (lane == 0) {
            float d0 = fmaxf(sqrtf(fn0), 1e-8f) * fmaxf(sqrtf(cn0), 1e-8f);
            float d1 = fmaxf(sqrtf(fn1), 1e-8f) * fmaxf(sqrtf(cn1), 1e-8f);
            out[1 + r0] = dt0 / d0;
            out[1 + r1] = dt1 / d1;
            // sum of squared diffs: ||f||^2 - 2 f.c + ||c||^2  (both rows)
            sh[warp] = (fn0 - 2.f * dt0 + cn0) + (fn1 - 2.f * dt1 + cn1);
        }
        __syncthreads();
        if (threadIdx.x == 0) {
            float t = 0.f;
            #pragma unroll
            for (int w = 0; w < 8; w++) t += sh[w];
            g_partials[blockIdx.x] = t;
        }
    } else {
        // ---- anchor stats: one block per v ----
        // pair_sum = C * sum_c ||a_c||^2 - ||sum_c a_c||^2 (pd diagonal is 0)
        const int v = blockIdx.x - MAIN_BLOCKS;
        const int t = threadIdx.x;          // 0..255, covers d and d+256
        const float* a = anchor + (size_t)v * NC * ND;

        float m0 = 0.f, m1 = 0.f, s = 0.f;
        #pragma unroll 4
        for (int c = 0; c < NC; c++) {
            float x0 = a[(size_t)c * ND + t];
            float x1 = a[(size_t)c * ND + t + 256];
            m0 += x0; m1 += x1;
            s = fmaf(x0, x0, fmaf(x1, x1, s));
        }
        float q = fmaf(m0, m0, m1 * m1);

        __shared__ float shs[256], shq[256];
        shs[t] = s; shq[t] = q;
        __syncthreads();
        #pragma unroll
        for (int off = 128; off > 0; off >>= 1) {
            if (t < off) { shs[t] += shs[t + off]; shq[t] += shq[t + off]; }
            __syncthreads();
        }
        if (t == 0) {
            float S = shs[0];          // sum_c ||a_c||^2
            float M2 = shq[0];         // ||sum_c a_c||^2
            float inter = (NC * S - M2) / (float)(NC * (NC - 1));
            g_inter[v] = fmaxf(MARGIN_F - inter, 0.0f);
        }
    }
}

__global__ void __launch_bounds__(256) anchor_loss_finalize(float* __restrict__ out)
{
    // PDL: launch overlaps with primary; block here until primary completes.
    cudaGridDependencySynchronize();

    const int t = threadIdx.x;  // 256 threads; 2048 partials as 512 float4
    const float4* p4 = reinterpret_cast<const float4*>(g_partials);
    float4 a = p4[t];                 // v=0 : partials [0,1024)   = float4 [0,256)
    float4 b = p4[t + 256];           // v=1 : partials [1024,2048)= float4 [256,512)
    float t0 = (a.x + a.y) + (a.z + a.w);
    float t1 = (b.x + b.y) + (b.z + b.w);

    __shared__ float s0[256], s1[256];
    s0[t] = t0; s1[t] = t1;
    __syncthreads();
    #pragma unroll
    for (int off = 128; off > 0; off >>= 1) {
        if (t < off) { s0[t] += s0[t + off]; s1[t] += s1[t + off]; }
        __syncthreads();
    }
    if (t == 0) {
        float center_mean = (s0[0] + s1[0]) / (2.0f * (float)NV * (float)NB);
        float inter_mean  = (g_inter[0] + g_inter[1]) / (float)NV;
        out[0] = center_mean + inter_mean;
    }
}

extern "C" void kernel_launch(void* const* d_in, const int* in_sizes, int n_in,
                              void* d_out, int out_size)
{
    const float* feat   = (const float*)d_in[0];
    const int*   label  = (const int*)d_in[1];
    const float* anchor = (const float*)d_in[2];
    float* out = (float*)d_out;

    anchor_loss_main<<<MAIN_BLOCKS + NV, 256>>>(feat, label, anchor, out);

    // Finalize with Programmatic Dependent Launch: its launch setup overlaps
    // with the primary kernel; the dependency wait happens on-device.
    cudaLaunchConfig_t cfg = {};
    cfg.gridDim  = dim3(1, 1, 1);
    cfg.blockDim = dim3(256, 1, 1);
    cfg.dynamicSmemBytes = 0;
    cfg.stream = 0;
    cudaLaunchAttribute attrs[1];
    attrs[0].id = cudaLaunchAttributeProgrammaticStreamSerialization;
    attrs[0].val.programmaticStreamSerializationAllowed = 1;
    cfg.attrs = attrs;
    cfg.numAttrs = 1;
    cudaLaunchKernelEx(&cfg, anchor_loss_finalize, out);
}